// round 11
// baseline (speedup 1.0000x reference)
#include <cuda_runtime.h>
#include <cuda_fp16.h>
#include <math.h>
#include <stdint.h>

#define Bc     8
#define Cc     256
#define Hc     128
#define Wc     128
#define INTERc 64
#define HWc    (Hc*Wc)     // 16384
#define BHWc   (Bc*HWc)    // 131072

// ---------------- scratch (static __device__, no allocs) ----------------
__device__ float g_xe[Bc*INTERc*HWc];
__device__ float g_xq[Bc*INTERc*HWc];
__device__ float g_q [BHWc*8];            // [b][h][w][8]
__device__ float g_k [BHWc*8];            // [b][h][w][8]
__device__ float g_vA[BHWc*INTERc];       // [b][w][h][64]
__device__ float g_vB[BHWc*INTERc];       // [b][h][w][64]
__device__ float g_OH[BHWc*INTERc];       // [b][w][h][64]
__device__ float g_OW[BHWc*INTERc];       // [b][h][w][64]
__device__ float g_mH[BHWc];
__device__ float g_sH[BHWc];
__device__ float g_mW[BHWc];
__device__ float g_sW[BHWc];
// fp16 weights in m16n8k16 fragment order: [ocb][cig][rs][ks][lane][2*NT] half2
__device__ __align__(16) uint32_t g_wkE[73728];
__device__ __align__(16) uint32_t g_wkQ[73728];
__device__ __align__(16) uint32_t g_wkTE[73728];
__device__ __align__(16) uint32_t g_wkTQ[73728];

// ---------------- helpers ----------------
__device__ __forceinline__ void mma_f16(float* c, const uint32_t* a, uint32_t b0, uint32_t b1) {
    asm volatile("mma.sync.aligned.m16n8k16.row.col.f32.f16.f16.f32 "
        "{%0,%1,%2,%3}, {%4,%5,%6,%7}, {%8,%9}, {%0,%1,%2,%3};"
        : "+f"(c[0]), "+f"(c[1]), "+f"(c[2]), "+f"(c[3])
        : "r"(a[0]), "r"(a[1]), "r"(a[2]), "r"(a[3]), "r"(b0), "r"(b1));
}
__device__ __forceinline__ uint32_t pack_h2(float lo, float hi) {
    __half2 h = __floats2half2_rn(lo, hi);
    return *(uint32_t*)&h;
}

// ---- weight prep: OIHW -> k16 fragment-order [ocb][cig][rs][ks][lane][2NT] --
__global__ void prep_frag16(const float* __restrict__ w, uint32_t* __restrict__ wf,
                            int CIN_, int COUT_TILE_, int total)
{
    int idx = blockIdx.x * 256 + threadIdx.x;
    if (idx >= total) return;
    int NT2_ = COUT_TILE_ / 4;           // 2*NT regs per lane per ks
    int j    = idx % NT2_;  int t1 = idx / NT2_;
    int lane = t1 % 32;     int t2 = t1 / 32;
    int ks   = t2 % 2;      int t3 = t2 / 2;
    int rs   = t3 % 9;      int t4 = t3 / 9;
    int NCIG_ = CIN_ / 32;
    int cig  = t4 % NCIG_;  int ocb = t4 / NCIG_;
    int nt   = j >> 1, b01 = j & 1;
    int tig  = lane & 3, gid = lane >> 2;
    int ci   = cig*32 + ks*16 + b01*8 + tig*2;
    int oc   = ocb*COUT_TILE_ + nt*8 + gid;
    float lo = w[((size_t)oc*CIN_ + ci    )*9 + rs];
    float hi = w[((size_t)oc*CIN_ + ci + 1)*9 + rs];
    wf[idx] = pack_h2(lo, hi);
}

// ------------ fp16 tensor-core implicit-GEMM 3x3 conv + BN + ReLU ------------
// CTA: one (b,h) row (x oc-half for tail). M=128 px, N=COUT_TILE, K=CIN*9.
// raw staged as half2 ci-pairs; B staged in SMEM fragment order, prefetched.
template<int CIN, int COUT_TILE, int NSPLIT>
__global__ __launch_bounds__(256)
void conv_mma16(const float* __restrict__ x, const uint32_t* __restrict__ wf,
                const float* __restrict__ sc, const float* __restrict__ bi,
                float* __restrict__ y)
{
    constexpr int NCIG   = CIN / 32;
    constexpr int T      = NCIG * 9;
    constexpr int NT     = COUT_TILE / 8;
    constexpr int NT2    = 2 * NT;
    constexpr int PR2    = 136;              // raw2 pitch (uint32), conflict-free
    constexpr int RAW2   = 48 * PR2;         // 3 rows x 16 ci-pairs
    constexpr int PBL2   = NT2 + 4;          // Bs lane pitch (20 / 36)
    constexpr int STEPP2 = 32 * PBL2;        // smem uint32 per ks block
    constexpr int STEPG  = 2 * 32 * NT2;     // global uint32 per (cig,rs) step
    constexpr int V      = STEPG / 256;      // uint32 per thread per step
    constexpr int NV4    = V / 4;
    constexpr int COUT   = COUT_TILE * NSPLIT;

    extern __shared__ uint32_t smu[];
    uint32_t* raw2 = smu;                    // [48][136] half2
    uint32_t* Bs   = smu + RAW2;             // [2][32][PBL2]
    float*    Cs   = (float*)smu;            // epilogue alias: [COUT_TILE][132]

    const int tid  = threadIdx.x;
    const int warp = tid >> 5, lane = tid & 31;
    const int gid  = lane >> 2, tig = lane & 3;
    const int h   = blockIdx.x;
    const int b   = blockIdx.y;
    const int ocb = blockIdx.z;
    const int px0 = warp * 16 + gid;

    float C[NT][4];
    #pragma unroll
    for (int nt = 0; nt < NT; nt++)
        #pragma unroll
        for (int i = 0; i < 4; i++) C[nt][i] = 0.f;

    // per-thread smem addresses for its V-uint32 slice of a B step
    int sAddr[NV4];
    #pragma unroll
    for (int v = 0; v < NV4; v++) {
        int f    = tid * V + v * 4;
        int ks   = f / (32*NT2);
        int rem  = f % (32*NT2);
        sAddr[v] = ks * STEPP2 + (rem / NT2) * PBL2 + (rem % NT2);
    }

    uint4 bpre[NV4];
    auto loadB = [&](int t) {
        if (t < T) {
            const uint4* p = (const uint4*)(wf + ((size_t)ocb*T + t)*STEPG + tid*V);
            #pragma unroll
            for (int v = 0; v < NV4; v++) bpre[v] = p[v];
        }
    };
    loadB(0);

    for (int cig = 0; cig < NCIG; cig++) {
        __syncthreads();   // prev mma done reading raw2
        // ---- stage raw2: 3 rows x 16 ci-pairs, cols 0..129 = w(-1..128)
        for (int rr = warp; rr < 48; rr += 8) {
            int r = rr >> 4, ci2 = rr & 15;
            int gh = h - 1 + r;
            bool rowok = (gh >= 0) && (gh < Hc);
            const float* s0 = x + (((size_t)b*CIN + cig*32 + ci2*2)*Hc + gh)*Wc;
            const float* s1 = s0 + HWc;
            uint32_t* dst = raw2 + rr * PR2;
            #pragma unroll
            for (int k = 0; k < 5; k++) {
                int c = lane + 32*k;
                if (c < 130) {
                    int gw = c - 1;
                    bool ok = rowok && gw >= 0 && gw < Wc;
                    float v0 = ok ? s0[gw] : 0.f;
                    float v1 = ok ? s1[gw] : 0.f;
                    dst[c] = pack_h2(v0, v1);
                }
            }
        }

        for (int rs = 0; rs < 9; rs++) {
            __syncthreads();      // prev mma done reading Bs; raw staged (rs==0)
            #pragma unroll
            for (int v = 0; v < NV4; v++)
                *(uint4*)(Bs + sAddr[v]) = bpre[v];
            loadB(cig*9 + rs + 1);
            __syncthreads();      // Bs (and raw2) published

            const int r = rs / 3, s = rs - r*3;
            #pragma unroll
            for (int ks = 0; ks < 2; ks++) {
                const uint32_t* ra = raw2 + (r*16 + ks*8 + tig)*PR2 + px0 + s;
                uint32_t a[4];
                a[0] = ra[0];
                a[1] = ra[8];
                a[2] = ra[4*PR2];
                a[3] = ra[4*PR2 + 8];
                const uint4* bs4 = (const uint4*)(Bs + ks*STEPP2 + lane*PBL2);
                #pragma unroll
                for (int q = 0; q < NT/2; q++) {
                    uint4 bv = bs4[q];
                    mma_f16(C[2*q  ], a, bv.x, bv.y);
                    mma_f16(C[2*q+1], a, bv.z, bv.w);
                }
            }
        }
    }

    // ---- epilogue: frags -> SMEM (aliased), then coalesced BN+ReLU stores
    __syncthreads();
    #pragma unroll
    for (int nt = 0; nt < NT; nt++) {
        int oc = nt*8 + 2*tig;
        Cs[(oc  )*132 + px0    ] = C[nt][0];
        Cs[(oc+1)*132 + px0    ] = C[nt][1];
        Cs[(oc  )*132 + px0 + 8] = C[nt][2];
        Cs[(oc+1)*132 + px0 + 8] = C[nt][3];
    }
    __syncthreads();
    for (int idx = tid; idx < COUT_TILE*32; idx += 256) {
        int oc = idx >> 5, p4 = (idx & 31) * 4;
        float4 v = *(float4*)(Cs + oc*132 + p4);
        int ocg = ocb*COUT_TILE + oc;
        float s = __ldg(sc + ocg), bv = __ldg(bi + ocg);
        v.x = fmaf(v.x, s, bv); v.x = v.x > 0.f ? v.x : 0.f;
        v.y = fmaf(v.y, s, bv); v.y = v.y > 0.f ? v.y : 0.f;
        v.z = fmaf(v.z, s, bv); v.z = v.z > 0.f ? v.z : 0.f;
        v.w = fmaf(v.w, s, bv); v.w = v.w > 0.f ? v.w : 0.f;
        *(float4*)(y + (((size_t)b*COUT + ocg)*Hc + h)*Wc + p4) = v;
    }
}

// ---------------- QKV projection (pointwise) ----------------
__global__ __launch_bounds__(256)
void qkv_kernel(const float* __restrict__ xe, const float* __restrict__ xq,
                const float* __restrict__ qw, const float* __restrict__ qb,
                const float* __restrict__ kw, const float* __restrict__ kb,
                const float* __restrict__ vw, const float* __restrict__ vb,
                float* __restrict__ qo, float* __restrict__ ko,
                float* __restrict__ vA, float* __restrict__ vB)
{
    __shared__ float qwT[64][8], kwT[64][8], vwT[64][64];
    __shared__ float qbs[8], kbs[8], vbs[64];
    const int tid = threadIdx.x;
    for (int idx = tid; idx < 512; idx += 256) {
        int o = idx >> 6, ci = idx & 63;
        qwT[ci][o] = qw[idx];
        kwT[ci][o] = kw[idx];
    }
    for (int idx = tid; idx < 4096; idx += 256) {
        int o = idx >> 6, ci = idx & 63;
        vwT[ci][o] = vw[idx];
    }
    if (tid < 8)  { qbs[tid] = qb[tid]; kbs[tid] = kb[tid]; }
    if (tid < 64) vbs[tid] = vb[tid];
    __syncthreads();

    const int pix = blockIdx.x*256 + tid;
    const int b = pix >> 14, hw = pix & 16383;
    const int h = hw >> 7,   w  = hw & 127;

    float aq[8], ak[8], av[64];
    #pragma unroll
    for (int o = 0; o < 8; o++)  { aq[o] = qbs[o]; ak[o] = kbs[o]; }
    #pragma unroll
    for (int o = 0; o < 64; o++) av[o] = vbs[o];

    const float* xqp = xq + b*64*HWc + hw;
    const float* xep = xe + b*64*HWc + hw;
    #pragma unroll 1
    for (int ci = 0; ci < 64; ci++) {
        float xqv = xqp[ci*HWc];
        float xev = xep[ci*HWc];
        #pragma unroll
        for (int o = 0; o < 8; o++) {
            aq[o] = fmaf(qwT[ci][o], xqv, aq[o]);
            ak[o] = fmaf(kwT[ci][o], xev, ak[o]);
        }
        #pragma unroll
        for (int o = 0; o < 64; o++) av[o] = fmaf(vwT[ci][o], xev, av[o]);
    }

    float4* q4 = (float4*)(qo + pix*8);
    float4* k4 = (float4*)(ko + pix*8);
    q4[0] = make_float4(aq[0],aq[1],aq[2],aq[3]);
    q4[1] = make_float4(aq[4],aq[5],aq[6],aq[7]);
    k4[0] = make_float4(ak[0],ak[1],ak[2],ak[3]);
    k4[1] = make_float4(ak[4],ak[5],ak[6],ak[7]);

    float* vAp = vA + ((b*Wc + w)*Hc + h)*64;
    float* vBp = vB + pix*64;
    #pragma unroll
    for (int o = 0; o < 64; o += 4) {
        float4 t = make_float4(av[o],av[o+1],av[o+2],av[o+3]);
        *(float4*)(vAp + o) = t;
        *(float4*)(vBp + o) = t;
    }
}

// ---------------- axis attention (partial softmax + P@V) ----------------
// P stored pitch-128 with 16B-block XOR swizzle keyed on (i>>3)&7.
template<bool MASKD>
__global__ __launch_bounds__(256)
void attn_kernel(const float* __restrict__ q, const float* __restrict__ k,
                 const float* __restrict__ v, float* __restrict__ o,
                 float* __restrict__ mo, float* __restrict__ so)
{
    extern __shared__ float sm[];
    float* Qs = sm;                 // [8][128] transposed
    float* Ks = sm + 1024;          // [8][128]
    float* Vs = sm + 2048;          // [128][64]
    float* P  = sm + 2048 + 8192;   // [128][128] swizzled

    const int tid = threadIdx.x;
    const int x = blockIdx.x, b = blockIdx.y;

    int ibase, istride;
    if (MASKD) { ibase = (b*HWc + x)*8;     istride = Wc*8; }
    else       { ibase = (b*HWc + x*Wc)*8;  istride = 8;    }
    const int vbase  = (b*HWc + x*Hc)*64;
    const int msbase = b*HWc + x*Hc;

    {
        int i = tid >> 1, c0 = (tid & 1) * 4;
        float4 tq = *(const float4*)(q + ibase + i*istride + c0);
        float4 tk = *(const float4*)(k + ibase + i*istride + c0);
        Qs[(c0+0)*128 + i] = tq.x; Qs[(c0+1)*128 + i] = tq.y;
        Qs[(c0+2)*128 + i] = tq.z; Qs[(c0+3)*128 + i] = tq.w;
        Ks[(c0+0)*128 + i] = tk.x; Ks[(c0+1)*128 + i] = tk.y;
        Ks[(c0+2)*128 + i] = tk.z; Ks[(c0+3)*128 + i] = tk.w;
    }
    for (int idx = tid; idx < 2048; idx += 256)
        ((float4*)Vs)[idx] = ((const float4*)(v + vbase))[idx];
    __syncthreads();

    const int warp = tid >> 5, lane = tid & 31;
    float p[4][16];
    #pragma unroll
    for (int jt = 0; jt < 4; jt++) {
        const int j = jt*32 + lane;
        float kv[8];
        #pragma unroll
        for (int c = 0; c < 8; c++) kv[c] = Ks[c*128 + j];
        #pragma unroll
        for (int il = 0; il < 16; il++) {
            const int i = warp*16 + il;
            float acc = 0.f;
            #pragma unroll
            for (int c = 0; c < 8; c++) acc = fmaf(Qs[c*128 + i], kv[c], acc);
            if (MASKD && j == i) acc = -INFINITY;
            p[jt][il] = acc;
        }
    }
    #pragma unroll
    for (int il = 0; il < 16; il++) {
        const int i = warp*16 + il;
        const int sw = (i >> 3) & 7;
        float m = fmaxf(fmaxf(p[0][il], p[1][il]), fmaxf(p[2][il], p[3][il]));
        #pragma unroll
        for (int off = 16; off > 0; off >>= 1)
            m = fmaxf(m, __shfl_xor_sync(0xffffffffu, m, off));
        float s = 0.f;
        #pragma unroll
        for (int jt = 0; jt < 4; jt++) {
            float e = __expf(p[jt][il] - m);
            p[jt][il] = e; s += e;
        }
        #pragma unroll
        for (int off = 16; off > 0; off >>= 1)
            s += __shfl_xor_sync(0xffffffffu, s, off);
        #pragma unroll
        for (int jt = 0; jt < 4; jt++) {
            const int j = jt*32 + lane;
            P[i*128 + (((j >> 2) ^ sw) << 2) + (j & 3)] = p[jt][il];
        }
        if (lane == 0) { mo[msbase + i] = m; so[msbase + i] = s; }
    }
    __syncthreads();

    // O[i][c] = sum_j P[i][j] * V[j][c]  via float4 P + float4 V
    const int i0 = (tid >> 4) * 8, c0 = (tid & 15) * 4;
    float4 acc[8];
    #pragma unroll
    for (int ii = 0; ii < 8; ii++) acc[ii] = make_float4(0.f,0.f,0.f,0.f);
    #pragma unroll 2
    for (int jb = 0; jb < 32; jb++) {
        float4 v0 = *(float4*)(Vs + (jb*4+0)*64 + c0);
        float4 v1 = *(float4*)(Vs + (jb*4+1)*64 + c0);
        float4 v2 = *(float4*)(Vs + (jb*4+2)*64 + c0);
        float4 v3 = *(float4*)(Vs + (jb*4+3)*64 + c0);
        #pragma unroll
        for (int ii = 0; ii < 8; ii++) {
            const int ri = i0 + ii;
            float4 pv = *(float4*)(P + ri*128 + ((jb ^ ((ri >> 3) & 7)) << 2));
            acc[ii].x = fmaf(pv.x, v0.x, acc[ii].x);
            acc[ii].y = fmaf(pv.x, v0.y, acc[ii].y);
            acc[ii].z = fmaf(pv.x, v0.z, acc[ii].z);
            acc[ii].w = fmaf(pv.x, v0.w, acc[ii].w);
            acc[ii].x = fmaf(pv.y, v1.x, acc[ii].x);
            acc[ii].y = fmaf(pv.y, v1.y, acc[ii].y);
            acc[ii].z = fmaf(pv.y, v1.z, acc[ii].z);
            acc[ii].w = fmaf(pv.y, v1.w, acc[ii].w);
            acc[ii].x = fmaf(pv.z, v2.x, acc[ii].x);
            acc[ii].y = fmaf(pv.z, v2.y, acc[ii].y);
            acc[ii].z = fmaf(pv.z, v2.z, acc[ii].z);
            acc[ii].w = fmaf(pv.z, v2.w, acc[ii].w);
            acc[ii].x = fmaf(pv.w, v3.x, acc[ii].x);
            acc[ii].y = fmaf(pv.w, v3.y, acc[ii].y);
            acc[ii].z = fmaf(pv.w, v3.z, acc[ii].z);
            acc[ii].w = fmaf(pv.w, v3.w, acc[ii].w);
        }
    }
    #pragma unroll
    for (int ii = 0; ii < 8; ii++)
        *(float4*)(o + vbase + (i0+ii)*64 + c0) = acc[ii];
}

// ---------------- merge (combine partial softmaxes, +2, residual) ------------
__global__ __launch_bounds__(256)
void merge_kernel(const float* __restrict__ OH, const float* __restrict__ OW,
                  const float* __restrict__ mH, const float* __restrict__ sH,
                  const float* __restrict__ mW, const float* __restrict__ sW,
                  float* __restrict__ xe, float* __restrict__ xq,
                  const float* __restrict__ g1p, const float* __restrict__ g2p)
{
    const int pix = blockIdx.x*256 + threadIdx.x;
    const int b = pix >> 14, hw = pix & 16383;
    const int h = hw >> 7,   w  = hw & 127;
    const int idxH = (b*Wc + w)*Hc + h;

    float mh = mH[idxH], sh = sH[idxH];
    float mw = mW[pix],  sw = sW[pix];
    float m  = fmaxf(mh, mw);
    float a  = __expf(mh - m), bb = __expf(mw - m);
    float inv = 1.f / (a*sh + bb*sw);
    float g1 = *g1p, g2 = *g2p;

    const float4* ohp = (const float4*)(OH + idxH*64);
    const float4* owp = (const float4*)(OW + pix*64);
    float* xep = xe + b*64*HWc + hw;
    float* xqp = xq + b*64*HWc + hw;

    #pragma unroll
    for (int c4 = 0; c4 < 16; c4++) {
        float4 oh = ohp[c4], ow = owp[c4];
        float s0 = fmaf(a, oh.x, bb*ow.x)*inv + 2.f;
        float s1 = fmaf(a, oh.y, bb*ow.y)*inv + 2.f;
        float s2 = fmaf(a, oh.z, bb*ow.z)*inv + 2.f;
        float s3 = fmaf(a, oh.w, bb*ow.w)*inv + 2.f;
        int c = c4*4;
        xep[(c+0)*HWc] = fmaf(g1, s0, xep[(c+0)*HWc]);
        xep[(c+1)*HWc] = fmaf(g1, s1, xep[(c+1)*HWc]);
        xep[(c+2)*HWc] = fmaf(g1, s2, xep[(c+2)*HWc]);
        xep[(c+3)*HWc] = fmaf(g1, s3, xep[(c+3)*HWc]);
        xqp[(c+0)*HWc] = fmaf(g2, s0, xqp[(c+0)*HWc]);
        xqp[(c+1)*HWc] = fmaf(g2, s1, xqp[(c+1)*HWc]);
        xqp[(c+2)*HWc] = fmaf(g2, s2, xqp[(c+2)*HWc]);
        xqp[(c+3)*HWc] = fmaf(g2, s3, xqp[(c+3)*HWc]);
    }
}

// ---------------- launch ----------------
extern "C" void kernel_launch(void* const* d_in, const int* in_sizes, int n_in,
                              void* d_out, int out_size)
{
    const float* x_ex   = (const float*)d_in[0];
    const float* x_qr   = (const float*)d_in[1];
    const float* cexw   = (const float*)d_in[2];
    const float* bexs   = (const float*)d_in[3];
    const float* bexb   = (const float*)d_in[4];
    const float* cqw    = (const float*)d_in[5];
    const float* bqs    = (const float*)d_in[6];
    const float* bqb    = (const float*)d_in[7];
    const float* qw     = (const float*)d_in[8];
    const float* qb     = (const float*)d_in[9];
    const float* kw     = (const float*)d_in[10];
    const float* kb     = (const float*)d_in[11];
    const float* vw     = (const float*)d_in[12];
    const float* vb     = (const float*)d_in[13];
    const float* g1     = (const float*)d_in[14];
    const float* g2     = (const float*)d_in[15];
    const float* texw   = (const float*)d_in[16];
    const float* btexs  = (const float*)d_in[17];
    const float* btexb  = (const float*)d_in[18];
    const float* tqw    = (const float*)d_in[19];
    const float* btqs   = (const float*)d_in[20];
    const float* btqb   = (const float*)d_in[21];
    float* out = (float*)d_out;

    float *p_xe,*p_xq,*p_q,*p_k,*p_vA,*p_vB,*p_OH,*p_OW,*p_mH,*p_sH,*p_mW,*p_sW;
    uint32_t *p_wkE,*p_wkQ,*p_wkTE,*p_wkTQ;
    cudaGetSymbolAddress((void**)&p_xe, g_xe);
    cudaGetSymbolAddress((void**)&p_xq, g_xq);
    cudaGetSymbolAddress((void**)&p_q,  g_q);
    cudaGetSymbolAddress((void**)&p_k,  g_k);
    cudaGetSymbolAddress((void**)&p_vA, g_vA);
    cudaGetSymbolAddress((void**)&p_vB, g_vB);
    cudaGetSymbolAddress((void**)&p_OH, g_OH);
    cudaGetSymbolAddress((void**)&p_OW, g_OW);
    cudaGetSymbolAddress((void**)&p_mH, g_mH);
    cudaGetSymbolAddress((void**)&p_sH, g_sH);
    cudaGetSymbolAddress((void**)&p_mW, g_mW);
    cudaGetSymbolAddress((void**)&p_sW, g_sW);
    cudaGetSymbolAddress((void**)&p_wkE,  g_wkE);
    cudaGetSymbolAddress((void**)&p_wkQ,  g_wkQ);
    cudaGetSymbolAddress((void**)&p_wkTE, g_wkTE);
    cudaGetSymbolAddress((void**)&p_wkTQ, g_wkTQ);

    // smem bytes: mainloop vs epilogue (aliased) max
    // head: max((48*136 + 2*32*20)*4 = 31232, 64*132*4 = 33792)  = 33792
    // tail: max((48*136 + 2*32*36)*4 = 35328, 128*132*4 = 67584) = 67584
    const int head_smem = 64*132*4;
    const int tail_smem = 128*132*4;
    cudaFuncSetAttribute((const void*)conv_mma16<256,64,1>,
                         cudaFuncAttributeMaxDynamicSharedMemorySize, head_smem);
    cudaFuncSetAttribute((const void*)conv_mma16<64,128,2>,
                         cudaFuncAttributeMaxDynamicSharedMemorySize, tail_smem);
    const size_t attn_smem = (size_t)(1024 + 1024 + 8192 + 128*128) * sizeof(float);
    cudaFuncSetAttribute((const void*)attn_kernel<true>,
                         cudaFuncAttributeMaxDynamicSharedMemorySize, (int)attn_smem);
    cudaFuncSetAttribute((const void*)attn_kernel<false>,
                         cudaFuncAttributeMaxDynamicSharedMemorySize, (int)attn_smem);

    // weight prep: 73728 half2 regs each (9*CIN*COUT/2)
    prep_frag16<<<288, 256>>>(cexw, p_wkE, 256, 64, 73728);
    prep_frag16<<<288, 256>>>(cqw,  p_wkQ, 256, 64, 73728);
    prep_frag16<<<288, 256>>>(texw, p_wkTE, 64, 128, 73728);
    prep_frag16<<<288, 256>>>(tqw,  p_wkTQ, 64, 128, 73728);

    conv_mma16<256,64,1><<<dim3(Hc, Bc, 1), 256, head_smem>>>(x_ex, p_wkE, bexs, bexb, p_xe);
    conv_mma16<256,64,1><<<dim3(Hc, Bc, 1), 256, head_smem>>>(x_qr, p_wkQ, bqs,  bqb,  p_xq);

    for (int it = 0; it < 2; it++) {
        qkv_kernel<<<BHWc/256, 256>>>(p_xe, p_xq, qw, qb, kw, kb, vw, vb,
                                      p_q, p_k, p_vA, p_vB);
        attn_kernel<true ><<<dim3(Wc, Bc), 256, attn_smem>>>(p_q, p_k, p_vA, p_OH, p_mH, p_sH);
        attn_kernel<false><<<dim3(Hc, Bc), 256, attn_smem>>>(p_q, p_k, p_vB, p_OW, p_mW, p_sW);
        merge_kernel<<<BHWc/256, 256>>>(p_OH, p_OW, p_mH, p_sH, p_mW, p_sW,
                                        p_xe, p_xq, g1, g2);
    }

    conv_mma16<64,128,2><<<dim3(Hc, Bc, 2), 256, tail_smem>>>(p_xe, p_wkTE, btexs, btexb, out);
    conv_mma16<64,128,2><<<dim3(Hc, Bc, 2), 256, tail_smem>>>(p_xq, p_wkTQ, btqs, btqb,
                                                              out + (size_t)Bc*Cc*HWc);
}

// round 12
// speedup vs baseline: 1.5076x; 1.5076x over previous
#include <cuda_runtime.h>
#include <cuda_fp16.h>
#include <math.h>
#include <stdint.h>

#define Bc     8
#define Cc     256
#define Hc     128
#define Wc     128
#define INTERc 64
#define HWc    (Hc*Wc)     // 16384
#define BHWc   (Bc*HWc)    // 131072

// ---------------- scratch (static __device__, no allocs) ----------------
__device__ float g_xe[Bc*INTERc*HWc];
__device__ float g_xq[Bc*INTERc*HWc];
__device__ float g_q [BHWc*8];            // [b][h][w][8]
__device__ float g_k [BHWc*8];            // [b][h][w][8]
__device__ float g_vA[BHWc*INTERc];       // [b][w][h][64]
__device__ float g_vB[BHWc*INTERc];       // [b][h][w][64]
__device__ float g_OH[BHWc*INTERc];       // [b][w][h][64]
__device__ float g_OW[BHWc*INTERc];       // [b][h][w][64]
__device__ float g_mH[BHWc];
__device__ float g_sH[BHWc];
__device__ float g_mW[BHWc];
__device__ float g_sW[BHWc];
// fp16 weights in m16n8k16 fragment order: [ocb][cig][rs][ks][lane][2*NT] half2
__device__ __align__(16) uint32_t g_wkE[73728];
__device__ __align__(16) uint32_t g_wkQ[73728];
__device__ __align__(16) uint32_t g_wkTE[73728];
__device__ __align__(16) uint32_t g_wkTQ[73728];

// ---------------- helpers ----------------
__device__ __forceinline__ void mma_f16(float* c, const uint32_t* a, uint32_t b0, uint32_t b1) {
    asm volatile("mma.sync.aligned.m16n8k16.row.col.f32.f16.f16.f32 "
        "{%0,%1,%2,%3}, {%4,%5,%6,%7}, {%8,%9}, {%0,%1,%2,%3};"
        : "+f"(c[0]), "+f"(c[1]), "+f"(c[2]), "+f"(c[3])
        : "r"(a[0]), "r"(a[1]), "r"(a[2]), "r"(a[3]), "r"(b0), "r"(b1));
}
__device__ __forceinline__ uint32_t pack_h2(float lo, float hi) {
    __half2 h = __floats2half2_rn(lo, hi);
    return *(uint32_t*)&h;
}
__device__ __forceinline__ uint32_t smem_u32p(const void* p) {
    return (uint32_t)__cvta_generic_to_shared(p);
}
__device__ __forceinline__ void cp_async16(uint32_t dst, const void* src) {
    asm volatile("cp.async.cg.shared.global [%0], [%1], 16;" :: "r"(dst), "l"(src));
}
#define CP_COMMIT() asm volatile("cp.async.commit_group;" ::: "memory")
#define CP_WAIT0()  asm volatile("cp.async.wait_group 0;" ::: "memory")

// ---- weight prep: OIHW -> k16 fragment-order [ocb][cig][rs][ks][lane][2NT] --
__global__ void prep_frag16(const float* __restrict__ w, uint32_t* __restrict__ wf,
                            int CIN_, int COUT_TILE_, int total)
{
    int idx = blockIdx.x * 256 + threadIdx.x;
    if (idx >= total) return;
    int NT2_ = COUT_TILE_ / 4;           // 2*NT regs per lane per ks
    int j    = idx % NT2_;  int t1 = idx / NT2_;
    int lane = t1 % 32;     int t2 = t1 / 32;
    int ks   = t2 % 2;      int t3 = t2 / 2;
    int rs   = t3 % 9;      int t4 = t3 / 9;
    int NCIG_ = CIN_ / 32;
    int cig  = t4 % NCIG_;  int ocb = t4 / NCIG_;
    int nt   = j >> 1, b01 = j & 1;
    int tig  = lane & 3, gid = lane >> 2;
    int ci   = cig*32 + ks*16 + b01*8 + tig*2;
    int oc   = ocb*COUT_TILE_ + nt*8 + gid;
    float lo = w[((size_t)oc*CIN_ + ci    )*9 + rs];
    float hi = w[((size_t)oc*CIN_ + ci + 1)*9 + rs];
    wf[idx] = pack_h2(lo, hi);
}

// ------------ fp16 tensor-core implicit-GEMM 3x3 conv + BN + ReLU ------------
// CTA: one (b,h) row (x oc-half for tail). M=128 px, N=COUT_TILE, K=CIN*9.
// Whole-cig B staged via cp.async (one burst of 9*2*NT mma between barriers).
template<int CIN, int COUT_TILE, int NSPLIT>
__global__ __launch_bounds__(256)
void conv_mma16(const float* __restrict__ x, const uint32_t* __restrict__ wf,
                const float* __restrict__ sc, const float* __restrict__ bi,
                float* __restrict__ y)
{
    constexpr int NCIG  = CIN / 32;
    constexpr int NT    = COUT_TILE / 8;
    constexpr int NT2   = 2 * NT;
    constexpr int PR2   = 136;               // raw2 pitch (uint32), conflict-free
    constexpr int RAW2  = 48 * PR2;          // 3 rows x 16 ci-pairs = 6528 u32
    constexpr int PBL2  = NT2 + 4;           // Bs lane pitch (20 / 36)
    constexpr int SP    = 32 * PBL2;         // smem u32 per (rs,ks) block
    constexpr int CIGSZ = 9 * 2 * 32 * NT2;  // global u32 per cig
    constexpr int NCH   = CIGSZ / 4 / 256;   // 16B chunks per thread (9 / 18)
    constexpr int COUT  = COUT_TILE * NSPLIT;

    extern __shared__ uint32_t smu[];
    uint32_t* raw2 = smu;                    // [48][136] half2
    uint32_t* Bs   = smu + RAW2;             // [18][32][PBL2]
    float*    Cs   = (float*)smu;            // epilogue alias: [COUT_TILE][132]

    const int tid  = threadIdx.x;
    const int warp = tid >> 5, lane = tid & 31;
    const int gid  = lane >> 2, tig = lane & 3;
    const int h   = blockIdx.x;
    const int b   = blockIdx.y;
    const int ocb = blockIdx.z;
    const int px0 = warp * 16 + gid;

    float C[NT][4];
    #pragma unroll
    for (int nt = 0; nt < NT; nt++)
        #pragma unroll
        for (int i = 0; i < 4; i++) C[nt][i] = 0.f;

    // per-thread cp.async destinations (constant across cigs)
    const uint32_t bs_u32 = smem_u32p(Bs);
    uint32_t dstA[NCH];
    #pragma unroll
    for (int i = 0; i < NCH; i++) {
        int c4  = (tid + 256*i) * 4;           // first u32 of this 16B chunk
        int rk  = c4 / (32*NT2);               // (rs*2+ks)
        int rem = c4 % (32*NT2);
        dstA[i] = bs_u32 + (uint32_t)(rk*SP + (rem/NT2)*PBL2 + (rem%NT2)) * 4u;
    }

    for (int cig = 0; cig < NCIG; cig++) {
        __syncthreads();   // prev cig's mma done reading raw2 + Bs
        // ---- issue whole-cig B via cp.async (no registers)
        {
            const char* srcb = (const char*)(wf + ((size_t)(ocb*NCIG + cig))*CIGSZ)
                             + (size_t)tid*16;
            #pragma unroll
            for (int i = 0; i < NCH; i++)
                cp_async16(dstA[i], srcb + (size_t)i*256*16);
            CP_COMMIT();
        }
        // ---- stage raw2: 3 rows x 16 ci-pairs, cols 0..129 = w(-1..128)
        for (int rr = warp; rr < 48; rr += 8) {
            int r = rr >> 4, ci2 = rr & 15;
            int gh = h - 1 + r;
            bool rowok = (gh >= 0) && (gh < Hc);
            const float* s0 = x + (((size_t)b*CIN + cig*32 + ci2*2)*Hc + gh)*Wc;
            const float* s1 = s0 + HWc;
            uint32_t* dst = raw2 + rr * PR2;
            #pragma unroll
            for (int k = 0; k < 5; k++) {
                int c = lane + 32*k;
                if (c < 130) {
                    int gw = c - 1;
                    bool ok = rowok && gw >= 0 && gw < Wc;
                    float v0 = ok ? s0[gw] : 0.f;
                    float v1 = ok ? s1[gw] : 0.f;
                    dst[c] = pack_h2(v0, v1);
                }
            }
        }
        CP_WAIT0();
        __syncthreads();   // raw2 + Bs published

        // ---- unbroken mma burst: 9 rs x 2 ks x NT mma
        #pragma unroll
        for (int rs = 0; rs < 9; rs++) {
            const int r = rs / 3, s = rs - r*3;
            #pragma unroll
            for (int ks = 0; ks < 2; ks++) {
                const uint32_t* ra = raw2 + (r*16 + ks*8 + tig)*PR2 + px0 + s;
                uint32_t a[4];
                a[0] = ra[0];
                a[1] = ra[8];
                a[2] = ra[4*PR2];
                a[3] = ra[4*PR2 + 8];
                const uint4* bs4 = (const uint4*)(Bs + (rs*2 + ks)*SP + lane*PBL2);
                #pragma unroll
                for (int q = 0; q < NT/2; q++) {
                    uint4 bv = bs4[q];
                    mma_f16(C[2*q  ], a, bv.x, bv.y);
                    mma_f16(C[2*q+1], a, bv.z, bv.w);
                }
            }
        }
    }

    // ---- epilogue: frags -> SMEM (aliased), then coalesced BN+ReLU stores
    __syncthreads();
    #pragma unroll
    for (int nt = 0; nt < NT; nt++) {
        int oc = nt*8 + 2*tig;
        Cs[(oc  )*132 + px0    ] = C[nt][0];
        Cs[(oc+1)*132 + px0    ] = C[nt][1];
        Cs[(oc  )*132 + px0 + 8] = C[nt][2];
        Cs[(oc+1)*132 + px0 + 8] = C[nt][3];
    }
    __syncthreads();
    for (int idx = tid; idx < COUT_TILE*32; idx += 256) {
        int oc = idx >> 5, p4 = (idx & 31) * 4;
        float4 v = *(float4*)(Cs + oc*132 + p4);
        int ocg = ocb*COUT_TILE + oc;
        float s = __ldg(sc + ocg), bv = __ldg(bi + ocg);
        v.x = fmaf(v.x, s, bv); v.x = v.x > 0.f ? v.x : 0.f;
        v.y = fmaf(v.y, s, bv); v.y = v.y > 0.f ? v.y : 0.f;
        v.z = fmaf(v.z, s, bv); v.z = v.z > 0.f ? v.z : 0.f;
        v.w = fmaf(v.w, s, bv); v.w = v.w > 0.f ? v.w : 0.f;
        *(float4*)(y + (((size_t)b*COUT + ocg)*Hc + h)*Wc + p4) = v;
    }
}

// ---------------- QKV projection (pointwise) ----------------
__global__ __launch_bounds__(256)
void qkv_kernel(const float* __restrict__ xe, const float* __restrict__ xq,
                const float* __restrict__ qw, const float* __restrict__ qb,
                const float* __restrict__ kw, const float* __restrict__ kb,
                const float* __restrict__ vw, const float* __restrict__ vb,
                float* __restrict__ qo, float* __restrict__ ko,
                float* __restrict__ vA, float* __restrict__ vB)
{
    __shared__ float qwT[64][8], kwT[64][8], vwT[64][64];
    __shared__ float qbs[8], kbs[8], vbs[64];
    const int tid = threadIdx.x;
    for (int idx = tid; idx < 512; idx += 256) {
        int o = idx >> 6, ci = idx & 63;
        qwT[ci][o] = qw[idx];
        kwT[ci][o] = kw[idx];
    }
    for (int idx = tid; idx < 4096; idx += 256) {
        int o = idx >> 6, ci = idx & 63;
        vwT[ci][o] = vw[idx];
    }
    if (tid < 8)  { qbs[tid] = qb[tid]; kbs[tid] = kb[tid]; }
    if (tid < 64) vbs[tid] = vb[tid];
    __syncthreads();

    const int pix = blockIdx.x*256 + tid;
    const int b = pix >> 14, hw = pix & 16383;
    const int h = hw >> 7,   w  = hw & 127;

    float aq[8], ak[8], av[64];
    #pragma unroll
    for (int o = 0; o < 8; o++)  { aq[o] = qbs[o]; ak[o] = kbs[o]; }
    #pragma unroll
    for (int o = 0; o < 64; o++) av[o] = vbs[o];

    const float* xqp = xq + b*64*HWc + hw;
    const float* xep = xe + b*64*HWc + hw;
    #pragma unroll 1
    for (int ci = 0; ci < 64; ci++) {
        float xqv = xqp[ci*HWc];
        float xev = xep[ci*HWc];
        #pragma unroll
        for (int o = 0; o < 8; o++) {
            aq[o] = fmaf(qwT[ci][o], xqv, aq[o]);
            ak[o] = fmaf(kwT[ci][o], xev, ak[o]);
        }
        #pragma unroll
        for (int o = 0; o < 64; o++) av[o] = fmaf(vwT[ci][o], xev, av[o]);
    }

    float4* q4 = (float4*)(qo + pix*8);
    float4* k4 = (float4*)(ko + pix*8);
    q4[0] = make_float4(aq[0],aq[1],aq[2],aq[3]);
    q4[1] = make_float4(aq[4],aq[5],aq[6],aq[7]);
    k4[0] = make_float4(ak[0],ak[1],ak[2],ak[3]);
    k4[1] = make_float4(ak[4],ak[5],ak[6],ak[7]);

    float* vAp = vA + ((b*Wc + w)*Hc + h)*64;
    float* vBp = vB + pix*64;
    #pragma unroll
    for (int o = 0; o < 64; o += 4) {
        float4 t = make_float4(av[o],av[o+1],av[o+2],av[o+3]);
        *(float4*)(vAp + o) = t;
        *(float4*)(vBp + o) = t;
    }
}

// ---------------- axis attention (partial softmax + P@V) ----------------
// P stored pitch-128 with 16B-block XOR swizzle keyed on (i>>3)&7.
template<bool MASKD>
__global__ __launch_bounds__(256)
void attn_kernel(const float* __restrict__ q, const float* __restrict__ k,
                 const float* __restrict__ v, float* __restrict__ o,
                 float* __restrict__ mo, float* __restrict__ so)
{
    extern __shared__ float sm[];
    float* Qs = sm;                 // [8][128] transposed
    float* Ks = sm + 1024;          // [8][128]
    float* Vs = sm + 2048;          // [128][64]
    float* P  = sm + 2048 + 8192;   // [128][128] swizzled

    const int tid = threadIdx.x;
    const int x = blockIdx.x, b = blockIdx.y;

    int ibase, istride;
    if (MASKD) { ibase = (b*HWc + x)*8;     istride = Wc*8; }
    else       { ibase = (b*HWc + x*Wc)*8;  istride = 8;    }
    const int vbase  = (b*HWc + x*Hc)*64;
    const int msbase = b*HWc + x*Hc;

    {
        int i = tid >> 1, c0 = (tid & 1) * 4;
        float4 tq = *(const float4*)(q + ibase + i*istride + c0);
        float4 tk = *(const float4*)(k + ibase + i*istride + c0);
        Qs[(c0+0)*128 + i] = tq.x; Qs[(c0+1)*128 + i] = tq.y;
        Qs[(c0+2)*128 + i] = tq.z; Qs[(c0+3)*128 + i] = tq.w;
        Ks[(c0+0)*128 + i] = tk.x; Ks[(c0+1)*128 + i] = tk.y;
        Ks[(c0+2)*128 + i] = tk.z; Ks[(c0+3)*128 + i] = tk.w;
    }
    for (int idx = tid; idx < 2048; idx += 256)
        ((float4*)Vs)[idx] = ((const float4*)(v + vbase))[idx];
    __syncthreads();

    const int warp = tid >> 5, lane = tid & 31;
    float p[4][16];
    #pragma unroll
    for (int jt = 0; jt < 4; jt++) {
        const int j = jt*32 + lane;
        float kv[8];
        #pragma unroll
        for (int c = 0; c < 8; c++) kv[c] = Ks[c*128 + j];
        #pragma unroll
        for (int il = 0; il < 16; il++) {
            const int i = warp*16 + il;
            float acc = 0.f;
            #pragma unroll
            for (int c = 0; c < 8; c++) acc = fmaf(Qs[c*128 + i], kv[c], acc);
            if (MASKD && j == i) acc = -INFINITY;
            p[jt][il] = acc;
        }
    }
    #pragma unroll
    for (int il = 0; il < 16; il++) {
        const int i = warp*16 + il;
        const int sw = (i >> 3) & 7;
        float m = fmaxf(fmaxf(p[0][il], p[1][il]), fmaxf(p[2][il], p[3][il]));
        #pragma unroll
        for (int off = 16; off > 0; off >>= 1)
            m = fmaxf(m, __shfl_xor_sync(0xffffffffu, m, off));
        float s = 0.f;
        #pragma unroll
        for (int jt = 0; jt < 4; jt++) {
            float e = __expf(p[jt][il] - m);
            p[jt][il] = e; s += e;
        }
        #pragma unroll
        for (int off = 16; off > 0; off >>= 1)
            s += __shfl_xor_sync(0xffffffffu, s, off);
        #pragma unroll
        for (int jt = 0; jt < 4; jt++) {
            const int j = jt*32 + lane;
            P[i*128 + (((j >> 2) ^ sw) << 2) + (j & 3)] = p[jt][il];
        }
        if (lane == 0) { mo[msbase + i] = m; so[msbase + i] = s; }
    }
    __syncthreads();

    // O[i][c] = sum_j P[i][j] * V[j][c]  via float4 P + float4 V
    const int i0 = (tid >> 4) * 8, c0 = (tid & 15) * 4;
    float4 acc[8];
    #pragma unroll
    for (int ii = 0; ii < 8; ii++) acc[ii] = make_float4(0.f,0.f,0.f,0.f);
    #pragma unroll 2
    for (int jb = 0; jb < 32; jb++) {
        float4 v0 = *(float4*)(Vs + (jb*4+0)*64 + c0);
        float4 v1 = *(float4*)(Vs + (jb*4+1)*64 + c0);
        float4 v2 = *(float4*)(Vs + (jb*4+2)*64 + c0);
        float4 v3 = *(float4*)(Vs + (jb*4+3)*64 + c0);
        #pragma unroll
        for (int ii = 0; ii < 8; ii++) {
            const int ri = i0 + ii;
            float4 pv = *(float4*)(P + ri*128 + ((jb ^ ((ri >> 3) & 7)) << 2));
            acc[ii].x = fmaf(pv.x, v0.x, acc[ii].x);
            acc[ii].y = fmaf(pv.x, v0.y, acc[ii].y);
            acc[ii].z = fmaf(pv.x, v0.z, acc[ii].z);
            acc[ii].w = fmaf(pv.x, v0.w, acc[ii].w);
            acc[ii].x = fmaf(pv.y, v1.x, acc[ii].x);
            acc[ii].y = fmaf(pv.y, v1.y, acc[ii].y);
            acc[ii].z = fmaf(pv.y, v1.z, acc[ii].z);
            acc[ii].w = fmaf(pv.y, v1.w, acc[ii].w);
            acc[ii].x = fmaf(pv.z, v2.x, acc[ii].x);
            acc[ii].y = fmaf(pv.z, v2.y, acc[ii].y);
            acc[ii].z = fmaf(pv.z, v2.z, acc[ii].z);
            acc[ii].w = fmaf(pv.z, v2.w, acc[ii].w);
            acc[ii].x = fmaf(pv.w, v3.x, acc[ii].x);
            acc[ii].y = fmaf(pv.w, v3.y, acc[ii].y);
            acc[ii].z = fmaf(pv.w, v3.z, acc[ii].z);
            acc[ii].w = fmaf(pv.w, v3.w, acc[ii].w);
        }
    }
    #pragma unroll
    for (int ii = 0; ii < 8; ii++)
        *(float4*)(o + vbase + (i0+ii)*64 + c0) = acc[ii];
}

// ---------------- merge (combine partial softmaxes, +2, residual) ------------
__global__ __launch_bounds__(256)
void merge_kernel(const float* __restrict__ OH, const float* __restrict__ OW,
                  const float* __restrict__ mH, const float* __restrict__ sH,
                  const float* __restrict__ mW, const float* __restrict__ sW,
                  float* __restrict__ xe, float* __restrict__ xq,
                  const float* __restrict__ g1p, const float* __restrict__ g2p)
{
    const int pix = blockIdx.x*256 + threadIdx.x;
    const int b = pix >> 14, hw = pix & 16383;
    const int h = hw >> 7,   w  = hw & 127;
    const int idxH = (b*Wc + w)*Hc + h;

    float mh = mH[idxH], sh = sH[idxH];
    float mw = mW[pix],  sw = sW[pix];
    float m  = fmaxf(mh, mw);
    float a  = __expf(mh - m), bb = __expf(mw - m);
    float inv = 1.f / (a*sh + bb*sw);
    float g1 = *g1p, g2 = *g2p;

    const float4* ohp = (const float4*)(OH + idxH*64);
    const float4* owp = (const float4*)(OW + pix*64);
    float* xep = xe + b*64*HWc + hw;
    float* xqp = xq + b*64*HWc + hw;

    #pragma unroll
    for (int c4 = 0; c4 < 16; c4++) {
        float4 oh = ohp[c4], ow = owp[c4];
        float s0 = fmaf(a, oh.x, bb*ow.x)*inv + 2.f;
        float s1 = fmaf(a, oh.y, bb*ow.y)*inv + 2.f;
        float s2 = fmaf(a, oh.z, bb*ow.z)*inv + 2.f;
        float s3 = fmaf(a, oh.w, bb*ow.w)*inv + 2.f;
        int c = c4*4;
        xep[(c+0)*HWc] = fmaf(g1, s0, xep[(c+0)*HWc]);
        xep[(c+1)*HWc] = fmaf(g1, s1, xep[(c+1)*HWc]);
        xep[(c+2)*HWc] = fmaf(g1, s2, xep[(c+2)*HWc]);
        xep[(c+3)*HWc] = fmaf(g1, s3, xep[(c+3)*HWc]);
        xqp[(c+0)*HWc] = fmaf(g2, s0, xqp[(c+0)*HWc]);
        xqp[(c+1)*HWc] = fmaf(g2, s1, xqp[(c+1)*HWc]);
        xqp[(c+2)*HWc] = fmaf(g2, s2, xqp[(c+2)*HWc]);
        xqp[(c+3)*HWc] = fmaf(g2, s3, xqp[(c+3)*HWc]);
    }
}

// ---------------- launch ----------------
extern "C" void kernel_launch(void* const* d_in, const int* in_sizes, int n_in,
                              void* d_out, int out_size)
{
    const float* x_ex   = (const float*)d_in[0];
    const float* x_qr   = (const float*)d_in[1];
    const float* cexw   = (const float*)d_in[2];
    const float* bexs   = (const float*)d_in[3];
    const float* bexb   = (const float*)d_in[4];
    const float* cqw    = (const float*)d_in[5];
    const float* bqs    = (const float*)d_in[6];
    const float* bqb    = (const float*)d_in[7];
    const float* qw     = (const float*)d_in[8];
    const float* qb     = (const float*)d_in[9];
    const float* kw     = (const float*)d_in[10];
    const float* kb     = (const float*)d_in[11];
    const float* vw     = (const float*)d_in[12];
    const float* vb     = (const float*)d_in[13];
    const float* g1     = (const float*)d_in[14];
    const float* g2     = (const float*)d_in[15];
    const float* texw   = (const float*)d_in[16];
    const float* btexs  = (const float*)d_in[17];
    const float* btexb  = (const float*)d_in[18];
    const float* tqw    = (const float*)d_in[19];
    const float* btqs   = (const float*)d_in[20];
    const float* btqb   = (const float*)d_in[21];
    float* out = (float*)d_out;

    float *p_xe,*p_xq,*p_q,*p_k,*p_vA,*p_vB,*p_OH,*p_OW,*p_mH,*p_sH,*p_mW,*p_sW;
    uint32_t *p_wkE,*p_wkQ,*p_wkTE,*p_wkTQ;
    cudaGetSymbolAddress((void**)&p_xe, g_xe);
    cudaGetSymbolAddress((void**)&p_xq, g_xq);
    cudaGetSymbolAddress((void**)&p_q,  g_q);
    cudaGetSymbolAddress((void**)&p_k,  g_k);
    cudaGetSymbolAddress((void**)&p_vA, g_vA);
    cudaGetSymbolAddress((void**)&p_vB, g_vB);
    cudaGetSymbolAddress((void**)&p_OH, g_OH);
    cudaGetSymbolAddress((void**)&p_OW, g_OW);
    cudaGetSymbolAddress((void**)&p_mH, g_mH);
    cudaGetSymbolAddress((void**)&p_sH, g_sH);
    cudaGetSymbolAddress((void**)&p_mW, g_mW);
    cudaGetSymbolAddress((void**)&p_sW, g_sW);
    cudaGetSymbolAddress((void**)&p_wkE,  g_wkE);
    cudaGetSymbolAddress((void**)&p_wkQ,  g_wkQ);
    cudaGetSymbolAddress((void**)&p_wkTE, g_wkTE);
    cudaGetSymbolAddress((void**)&p_wkTQ, g_wkTQ);

    // smem bytes: mainloop vs epilogue (aliased) max
    // head: max((6528 + 18*32*20)*4 = 72192, 64*132*4 = 33792)    = 72192
    // tail: max((6528 + 18*32*36)*4 = 109056, 128*132*4 = 67584)  = 109056
    const int head_smem = (48*136 + 18*32*20) * 4;
    const int tail_smem = (48*136 + 18*32*36) * 4;
    cudaFuncSetAttribute((const void*)conv_mma16<256,64,1>,
                         cudaFuncAttributeMaxDynamicSharedMemorySize, head_smem);
    cudaFuncSetAttribute((const void*)conv_mma16<64,128,2>,
                         cudaFuncAttributeMaxDynamicSharedMemorySize, tail_smem);
    const size_t attn_smem = (size_t)(1024 + 1024 + 8192 + 128*128) * sizeof(float);
    cudaFuncSetAttribute((const void*)attn_kernel<true>,
                         cudaFuncAttributeMaxDynamicSharedMemorySize, (int)attn_smem);
    cudaFuncSetAttribute((const void*)attn_kernel<false>,
                         cudaFuncAttributeMaxDynamicSharedMemorySize, (int)attn_smem);

    // weight prep: 73728 half2 regs each (9*CIN*COUT/2)
    prep_frag16<<<288, 256>>>(cexw, p_wkE, 256, 64, 73728);
    prep_frag16<<<288, 256>>>(cqw,  p_wkQ, 256, 64, 73728);
    prep_frag16<<<288, 256>>>(texw, p_wkTE, 64, 128, 73728);
    prep_frag16<<<288, 256>>>(tqw,  p_wkTQ, 64, 128, 73728);

    conv_mma16<256,64,1><<<dim3(Hc, Bc, 1), 256, head_smem>>>(x_ex, p_wkE, bexs, bexb, p_xe);
    conv_mma16<256,64,1><<<dim3(Hc, Bc, 1), 256, head_smem>>>(x_qr, p_wkQ, bqs,  bqb,  p_xq);

    for (int it = 0; it < 2; it++) {
        qkv_kernel<<<BHWc/256, 256>>>(p_xe, p_xq, qw, qb, kw, kb, vw, vb,
                                      p_q, p_k, p_vA, p_vB);
        attn_kernel<true ><<<dim3(Wc, Bc), 256, attn_smem>>>(p_q, p_k, p_vA, p_OH, p_mH, p_sH);
        attn_kernel<false><<<dim3(Hc, Bc), 256, attn_smem>>>(p_q, p_k, p_vB, p_OW, p_mW, p_sW);
        merge_kernel<<<BHWc/256, 256>>>(p_OH, p_OW, p_mH, p_sH, p_mW, p_sW,
                                        p_xe, p_xq, g1, g2);
    }

    conv_mma16<64,128,2><<<dim3(Hc, Bc, 2), 256, tail_smem>>>(p_xe, p_wkTE, btexs, btexb, out);
    conv_mma16<64,128,2><<<dim3(Hc, Bc, 2), 256, tail_smem>>>(p_xq, p_wkTQ, btqs, btqb,
                                                              out + (size_t)Bc*Cc*HWc);
}

// round 16
// speedup vs baseline: 1.5544x; 1.0311x over previous
#include <cuda_runtime.h>
#include <cuda_fp16.h>
#include <math.h>
#include <stdint.h>

#define Bc     8
#define Cc     256
#define Hc     128
#define Wc     128
#define INTERc 64
#define HWc    (Hc*Wc)     // 16384
#define BHWc   (Bc*HWc)    // 131072

// ---------------- scratch (static __device__, no allocs) ----------------
__device__ float g_xe[Bc*INTERc*HWc];
__device__ float g_xq[Bc*INTERc*HWc];
__device__ float g_q [BHWc*8];            // [b][h][w][8]
__device__ float g_k [BHWc*8];            // [b][h][w][8]
__device__ float g_vA[BHWc*INTERc];       // [b][w][h][64]
__device__ float g_vB[BHWc*INTERc];       // [b][h][w][64]
__device__ float g_OH[BHWc*INTERc];       // [b][w][h][64]
__device__ float g_OW[BHWc*INTERc];       // [b][h][w][64]
__device__ float g_mH[BHWc];
__device__ float g_sH[BHWc];
__device__ float g_mW[BHWc];
__device__ float g_sW[BHWc];
// half2 channel-pair inputs: [b][ci2][h][w] u32
__device__ __align__(16) uint32_t g_xh2a[Bc*128*HWc];   // up to CIN=256
__device__ __align__(16) uint32_t g_xh2b[Bc*128*HWc];
// fp16 weights in m16n8k16 fragment order: [ocb][cig][rs][ks][lane][2*NT] half2
__device__ __align__(16) uint32_t g_wkE[73728];
__device__ __align__(16) uint32_t g_wkQ[73728];
__device__ __align__(16) uint32_t g_wkTE[73728];
__device__ __align__(16) uint32_t g_wkTQ[73728];

// ---------------- helpers ----------------
__device__ __forceinline__ void mma_f16(float* c, const uint32_t* a, uint32_t b0, uint32_t b1) {
    asm volatile("mma.sync.aligned.m16n8k16.row.col.f32.f16.f16.f32 "
        "{%0,%1,%2,%3}, {%4,%5,%6,%7}, {%8,%9}, {%0,%1,%2,%3};"
        : "+f"(c[0]), "+f"(c[1]), "+f"(c[2]), "+f"(c[3])
        : "r"(a[0]), "r"(a[1]), "r"(a[2]), "r"(a[3]), "r"(b0), "r"(b1));
}
__device__ __forceinline__ uint32_t pack_h2(float lo, float hi) {
    __half2 h = __floats2half2_rn(lo, hi);
    return *(uint32_t*)&h;
}
__device__ __forceinline__ uint32_t smem_u32p(const void* p) {
    return (uint32_t)__cvta_generic_to_shared(p);
}
__device__ __forceinline__ void cp_async16(uint32_t dst, const void* src) {
    asm volatile("cp.async.cg.shared.global [%0], [%1], 16;" :: "r"(dst), "l"(src));
}
#define CP_COMMIT() asm volatile("cp.async.commit_group;" ::: "memory")
#define CP_WAIT0()  asm volatile("cp.async.wait_group 0;" ::: "memory")

// ---- input prepass: NCHW f32 -> [b][ci2][h][w] half2(u32) channel pairs ----
__global__ void prep_half(const float* __restrict__ x, uint32_t* __restrict__ xh,
                          int total)
{
    int idx = blockIdx.x * 256 + threadIdx.x;
    if (idx >= total) return;
    int hw = idx & (HWc - 1);
    int t  = idx >> 14;                    // b*CIN2 + ci2
    float lo = x[(size_t)(2*t    )*HWc + hw];
    float hi = x[(size_t)(2*t + 1)*HWc + hw];
    xh[idx] = pack_h2(lo, hi);
}

// ---- weight prep: OIHW -> k16 fragment-order [ocb][cig][rs][ks][lane][2NT] --
__global__ void prep_frag16(const float* __restrict__ w, uint32_t* __restrict__ wf,
                            int CIN_, int COUT_TILE_, int total)
{
    int idx = blockIdx.x * 256 + threadIdx.x;
    if (idx >= total) return;
    int NT2_ = COUT_TILE_ / 4;           // 2*NT regs per lane per ks
    int j    = idx % NT2_;  int t1 = idx / NT2_;
    int lane = t1 % 32;     int t2 = t1 / 32;
    int ks   = t2 % 2;      int t3 = t2 / 2;
    int rs   = t3 % 9;      int t4 = t3 / 9;
    int NCIG_ = CIN_ / 32;
    int cig  = t4 % NCIG_;  int ocb = t4 / NCIG_;
    int nt   = j >> 1, b01 = j & 1;
    int tig  = lane & 3, gid = lane >> 2;
    int ci   = cig*32 + ks*16 + b01*8 + tig*2;
    int oc   = ocb*COUT_TILE_ + nt*8 + gid;
    float lo = w[((size_t)oc*CIN_ + ci    )*9 + rs];
    float hi = w[((size_t)oc*CIN_ + ci + 1)*9 + rs];
    wf[idx] = pack_h2(lo, hi);
}

// ------------ fp16 tensor-core implicit-GEMM 3x3 conv + BN + ReLU ------------
// CTA: one (b,h) row (x oc-half for tail). M=128 px, N=COUT_TILE, K=CIN*9.
// Raw panel AND whole-cig B staged via cp.async (unbroken mma burst per cig).
template<int CIN, int COUT_TILE, int NSPLIT>
__global__ __launch_bounds__(256)
void conv_mma16(const uint32_t* __restrict__ xh, const uint32_t* __restrict__ wf,
                const float* __restrict__ sc, const float* __restrict__ bi,
                float* __restrict__ y)
{
    constexpr int NCIG  = CIN / 32;
    constexpr int CIN2  = CIN / 2;
    constexpr int NT    = COUT_TILE / 8;
    constexpr int NT2   = 2 * NT;
    constexpr int PR2   = 136;               // raw2 pitch (uint32), conflict-free
    constexpr int RAW2  = 48 * PR2;          // 3 rows x 16 ci-pairs = 6528 u32
    constexpr int PBL2  = NT2 + 4;           // Bs lane pitch (20 / 36)
    constexpr int SP    = 32 * PBL2;         // smem u32 per (rs,ks) block
    constexpr int CIGSZ = 9 * 2 * 32 * NT2;  // global u32 per cig (weights)
    constexpr int NCH   = CIGSZ / 4 / 256;   // weight 16B chunks per thread
    constexpr int COUT  = COUT_TILE * NSPLIT;

    extern __shared__ uint32_t smu[];
    uint32_t* raw2 = smu;                    // [48][136]: data cols 4..131
    uint32_t* Bs   = smu + RAW2;             // [18][32][PBL2]
    float*    Cs   = (float*)smu;            // epilogue alias: [COUT_TILE][132]

    const int tid  = threadIdx.x;
    const int warp = tid >> 5, lane = tid & 31;
    const int gid  = lane >> 2, tig = lane & 3;
    const int h   = blockIdx.x;
    const int b   = blockIdx.y;
    const int ocb = blockIdx.z;
    const int px0 = warp * 16 + gid;

    float C[NT][4];
    #pragma unroll
    for (int nt = 0; nt < NT; nt++)
        #pragma unroll
        for (int i = 0; i < 4; i++) C[nt][i] = 0.f;

    // zero halo cols (gw=-1 -> idx 3, gw=128 -> idx 132); constant across cigs
    if (tid < 96) {
        int rr = tid % 48, c = (tid < 48) ? 3 : 132;
        raw2[rr*PR2 + c] = 0;
    }

    // per-thread cp.async B destinations (constant across cigs)
    const uint32_t bs_u32  = smem_u32p(Bs);
    const uint32_t raw_u32 = smem_u32p(raw2);
    uint32_t dstA[NCH];
    #pragma unroll
    for (int i = 0; i < NCH; i++) {
        int c4  = (tid + 256*i) * 4;           // first u32 of this 16B chunk
        int rk  = c4 / (32*NT2);               // (rs*2+ks)
        int rem = c4 % (32*NT2);
        dstA[i] = bs_u32 + (uint32_t)(rk*SP + (rem/NT2)*PBL2 + (rem%NT2)) * 4u;
    }

    for (int cig = 0; cig < NCIG; cig++) {
        __syncthreads();   // prev cig's mma done reading raw2 + Bs
        // ---- whole-cig B via cp.async
        {
            const char* srcb = (const char*)(wf + ((size_t)(ocb*NCIG + cig))*CIGSZ)
                             + (size_t)tid*16;
            #pragma unroll
            for (int i = 0; i < NCH; i++)
                cp_async16(dstA[i], srcb + (size_t)i*256*16);
        }
        // ---- raw panel via cp.async: 48 rows x 32 chunks of 16B
        {
            const uint32_t* xrow = xh + ((size_t)b*CIN2 + cig*16)*HWc;
            #pragma unroll
            for (int c = tid; c < 1536; c += 256) {
                int rr = c >> 5, k = c & 31;
                int r = rr >> 4, ci2 = rr & 15;
                int gh = h - 1 + r;
                uint32_t dst = raw_u32 + (uint32_t)(rr*PR2 + 4 + k*4) * 4u;
                if (gh >= 0 && gh < Hc) {
                    cp_async16(dst, xrow + ((size_t)ci2*Hc + gh)*Wc + k*4);
                } else {
                    *(uint4*)(raw2 + rr*PR2 + 4 + k*4) = make_uint4(0,0,0,0);
                }
            }
            CP_COMMIT();
        }
        CP_WAIT0();
        __syncthreads();   // raw2 + Bs published

        // ---- unbroken mma burst: 9 rs x 2 ks x NT mma
        #pragma unroll
        for (int rs = 0; rs < 9; rs++) {
            const int r = rs / 3, s = rs - r*3;
            #pragma unroll
            for (int ks = 0; ks < 2; ks++) {
                const uint32_t* ra = raw2 + (r*16 + ks*8 + tig)*PR2 + px0 + s + 3;
                uint32_t a[4];
                a[0] = ra[0];
                a[1] = ra[8];
                a[2] = ra[4*PR2];
                a[3] = ra[4*PR2 + 8];
                const uint4* bs4 = (const uint4*)(Bs + (rs*2 + ks)*SP + lane*PBL2);
                #pragma unroll
                for (int q = 0; q < NT/2; q++) {
                    uint4 bv = bs4[q];
                    mma_f16(C[2*q  ], a, bv.x, bv.y);
                    mma_f16(C[2*q+1], a, bv.z, bv.w);
                }
            }
        }
    }

    // ---- epilogue: frags -> SMEM (aliased), then coalesced BN+ReLU stores
    __syncthreads();
    #pragma unroll
    for (int nt = 0; nt < NT; nt++) {
        int oc = nt*8 + 2*tig;
        Cs[(oc  )*132 + px0    ] = C[nt][0];
        Cs[(oc+1)*132 + px0    ] = C[nt][1];
        Cs[(oc  )*132 + px0 + 8] = C[nt][2];
        Cs[(oc+1)*132 + px0 + 8] = C[nt][3];
    }
    __syncthreads();
    for (int idx = tid; idx < COUT_TILE*32; idx += 256) {
        int oc = idx >> 5, p4 = (idx & 31) * 4;
        float4 v = *(float4*)(Cs + oc*132 + p4);
        int ocg = ocb*COUT_TILE + oc;
        float s = __ldg(sc + ocg), bv = __ldg(bi + ocg);
        v.x = fmaf(v.x, s, bv); v.x = v.x > 0.f ? v.x : 0.f;
        v.y = fmaf(v.y, s, bv); v.y = v.y > 0.f ? v.y : 0.f;
        v.z = fmaf(v.z, s, bv); v.z = v.z > 0.f ? v.z : 0.f;
        v.w = fmaf(v.w, s, bv); v.w = v.w > 0.f ? v.w : 0.f;
        *(float4*)(y + (((size_t)b*COUT + ocg)*Hc + h)*Wc + p4) = v;
    }
}

// ---------------- QKV projection (pointwise) ----------------
__global__ __launch_bounds__(256)
void qkv_kernel(const float* __restrict__ xe, const float* __restrict__ xq,
                const float* __restrict__ qw, const float* __restrict__ qb,
                const float* __restrict__ kw, const float* __restrict__ kb,
                const float* __restrict__ vw, const float* __restrict__ vb,
                float* __restrict__ qo, float* __restrict__ ko,
                float* __restrict__ vA, float* __restrict__ vB)
{
    __shared__ float qwT[64][8], kwT[64][8], vwT[64][64];
    __shared__ float qbs[8], kbs[8], vbs[64];
    const int tid = threadIdx.x;
    for (int idx = tid; idx < 512; idx += 256) {
        int o = idx >> 6, ci = idx & 63;
        qwT[ci][o] = qw[idx];
        kwT[ci][o] = kw[idx];
    }
    for (int idx = tid; idx < 4096; idx += 256) {
        int o = idx >> 6, ci = idx & 63;
        vwT[ci][o] = vw[idx];
    }
    if (tid < 8)  { qbs[tid] = qb[tid]; kbs[tid] = kb[tid]; }
    if (tid < 64) vbs[tid] = vb[tid];
    __syncthreads();

    const int pix = blockIdx.x*256 + tid;
    const int b = pix >> 14, hw = pix & 16383;
    const int h = hw >> 7,   w  = hw & 127;

    float aq[8], ak[8], av[64];
    #pragma unroll
    for (int o = 0; o < 8; o++)  { aq[o] = qbs[o]; ak[o] = kbs[o]; }
    #pragma unroll
    for (int o = 0; o < 64; o++) av[o] = vbs[o];

    const float* xqp = xq + b*64*HWc + hw;
    const float* xep = xe + b*64*HWc + hw;
    #pragma unroll 1
    for (int ci = 0; ci < 64; ci++) {
        float xqv = xqp[ci*HWc];
        float xev = xep[ci*HWc];
        #pragma unroll
        for (int o = 0; o < 8; o++) {
            aq[o] = fmaf(qwT[ci][o], xqv, aq[o]);
            ak[o] = fmaf(kwT[ci][o], xev, ak[o]);
        }
        #pragma unroll
        for (int o = 0; o < 64; o++) av[o] = fmaf(vwT[ci][o], xev, av[o]);
    }

    float4* q4 = (float4*)(qo + pix*8);
    float4* k4 = (float4*)(ko + pix*8);
    q4[0] = make_float4(aq[0],aq[1],aq[2],aq[3]);
    q4[1] = make_float4(aq[4],aq[5],aq[6],aq[7]);
    k4[0] = make_float4(ak[0],ak[1],ak[2],ak[3]);
    k4[1] = make_float4(ak[4],ak[5],ak[6],ak[7]);

    float* vAp = vA + ((b*Wc + w)*Hc + h)*64;
    float* vBp = vB + pix*64;
    #pragma unroll
    for (int o = 0; o < 64; o += 4) {
        float4 t = make_float4(av[o],av[o+1],av[o+2],av[o+3]);
        *(float4*)(vAp + o) = t;
        *(float4*)(vBp + o) = t;
    }
}

// ---------------- axis attention (partial softmax + P@V) ----------------
// P stored pitch-128 with 16B-block XOR swizzle keyed on (i>>3)&7.
template<bool MASKD>
__global__ __launch_bounds__(256)
void attn_kernel(const float* __restrict__ q, const float* __restrict__ k,
                 const float* __restrict__ v, float* __restrict__ o,
                 float* __restrict__ mo, float* __restrict__ so)
{
    extern __shared__ float sm[];
    float* Qs = sm;                 // [8][128] transposed
    float* Ks = sm + 1024;          // [8][128]
    float* Vs = sm + 2048;          // [128][64]
    float* P  = sm + 2048 + 8192;   // [128][128] swizzled

    const int tid = threadIdx.x;
    const int x = blockIdx.x, b = blockIdx.y;

    int ibase, istride;
    if (MASKD) { ibase = (b*HWc + x)*8;     istride = Wc*8; }
    else       { ibase = (b*HWc + x*Wc)*8;  istride = 8;    }
    const int vbase  = (b*HWc + x*Hc)*64;
    const int msbase = b*HWc + x*Hc;

    {
        int i = tid >> 1, c0 = (tid & 1) * 4;
        float4 tq = *(const float4*)(q + ibase + i*istride + c0);
        float4 tk = *(const float4*)(k + ibase + i*istride + c0);
        Qs[(c0+0)*128 + i] = tq.x; Qs[(c0+1)*128 + i] = tq.y;
        Qs[(c0+2)*128 + i] = tq.z; Qs[(c0+3)*128 + i] = tq.w;
        Ks[(c0+0)*128 + i] = tk.x; Ks[(c0+1)*128 + i] = tk.y;
        Ks[(c0+2)*128 + i] = tk.z; Ks[(c0+3)*128 + i] = tk.w;
    }
    for (int idx = tid; idx < 2048; idx += 256)
        ((float4*)Vs)[idx] = ((const float4*)(v + vbase))[idx];
    __syncthreads();

    const int warp = tid >> 5, lane = tid & 31;
    float p[4][16];
    #pragma unroll
    for (int jt = 0; jt < 4; jt++) {
        const int j = jt*32 + lane;
        float kv[8];
        #pragma unroll
        for (int c = 0; c < 8; c++) kv[c] = Ks[c*128 + j];
        #pragma unroll
        for (int il = 0; il < 16; il++) {
            const int i = warp*16 + il;
            float acc = 0.f;
            #pragma unroll
            for (int c = 0; c < 8; c++) acc = fmaf(Qs[c*128 + i], kv[c], acc);
            if (MASKD && j == i) acc = -INFINITY;
            p[jt][il] = acc;
        }
    }
    #pragma unroll
    for (int il = 0; il < 16; il++) {
        const int i = warp*16 + il;
        const int sw = (i >> 3) & 7;
        float m = fmaxf(fmaxf(p[0][il], p[1][il]), fmaxf(p[2][il], p[3][il]));
        #pragma unroll
        for (int off = 16; off > 0; off >>= 1)
            m = fmaxf(m, __shfl_xor_sync(0xffffffffu, m, off));
        float s = 0.f;
        #pragma unroll
        for (int jt = 0; jt < 4; jt++) {
            float e = __expf(p[jt][il] - m);
            p[jt][il] = e; s += e;
        }
        #pragma unroll
        for (int off = 16; off > 0; off >>= 1)
            s += __shfl_xor_sync(0xffffffffu, s, off);
        #pragma unroll
        for (int jt = 0; jt < 4; jt++) {
            const int j = jt*32 + lane;
            P[i*128 + (((j >> 2) ^ sw) << 2) + (j & 3)] = p[jt][il];
        }
        if (lane == 0) { mo[msbase + i] = m; so[msbase + i] = s; }
    }
    __syncthreads();

    // O[i][c] = sum_j P[i][j] * V[j][c]  via float4 P + float4 V
    const int i0 = (tid >> 4) * 8, c0 = (tid & 15) * 4;
    float4 acc[8];
    #pragma unroll
    for (int ii = 0; ii < 8; ii++) acc[ii] = make_float4(0.f,0.f,0.f,0.f);
    #pragma unroll 2
    for (int jb = 0; jb < 32; jb++) {
        float4 v0 = *(float4*)(Vs + (jb*4+0)*64 + c0);
        float4 v1 = *(float4*)(Vs + (jb*4+1)*64 + c0);
        float4 v2 = *(float4*)(Vs + (jb*4+2)*64 + c0);
        float4 v3 = *(float4*)(Vs + (jb*4+3)*64 + c0);
        #pragma unroll
        for (int ii = 0; ii < 8; ii++) {
            const int ri = i0 + ii;
            float4 pv = *(float4*)(P + ri*128 + ((jb ^ ((ri >> 3) & 7)) << 2));
            acc[ii].x = fmaf(pv.x, v0.x, acc[ii].x);
            acc[ii].y = fmaf(pv.x, v0.y, acc[ii].y);
            acc[ii].z = fmaf(pv.x, v0.z, acc[ii].z);
            acc[ii].w = fmaf(pv.x, v0.w, acc[ii].w);
            acc[ii].x = fmaf(pv.y, v1.x, acc[ii].x);
            acc[ii].y = fmaf(pv.y, v1.y, acc[ii].y);
            acc[ii].z = fmaf(pv.y, v1.z, acc[ii].z);
            acc[ii].w = fmaf(pv.y, v1.w, acc[ii].w);
            acc[ii].x = fmaf(pv.z, v2.x, acc[ii].x);
            acc[ii].y = fmaf(pv.z, v2.y, acc[ii].y);
            acc[ii].z = fmaf(pv.z, v2.z, acc[ii].z);
            acc[ii].w = fmaf(pv.z, v2.w, acc[ii].w);
            acc[ii].x = fmaf(pv.w, v3.x, acc[ii].x);
            acc[ii].y = fmaf(pv.w, v3.y, acc[ii].y);
            acc[ii].z = fmaf(pv.w, v3.z, acc[ii].z);
            acc[ii].w = fmaf(pv.w, v3.w, acc[ii].w);
        }
    }
    #pragma unroll
    for (int ii = 0; ii < 8; ii++)
        *(float4*)(o + vbase + (i0+ii)*64 + c0) = acc[ii];
}

// ---------------- merge (combine partial softmaxes, +2, residual) ------------
__global__ __launch_bounds__(256)
void merge_kernel(const float* __restrict__ OH, const float* __restrict__ OW,
                  const float* __restrict__ mH, const float* __restrict__ sH,
                  const float* __restrict__ mW, const float* __restrict__ sW,
                  float* __restrict__ xe, float* __restrict__ xq,
                  const float* __restrict__ g1p, const float* __restrict__ g2p)
{
    const int pix = blockIdx.x*256 + threadIdx.x;
    const int b = pix >> 14, hw = pix & 16383;
    const int h = hw >> 7,   w  = hw & 127;
    const int idxH = (b*Wc + w)*Hc + h;

    float mh = mH[idxH], sh = sH[idxH];
    float mw = mW[pix],  sw = sW[pix];
    float m  = fmaxf(mh, mw);
    float a  = __expf(mh - m), bb = __expf(mw - m);
    float inv = 1.f / (a*sh + bb*sw);
    float g1 = *g1p, g2 = *g2p;

    const float4* ohp = (const float4*)(OH + idxH*64);
    const float4* owp = (const float4*)(OW + pix*64);
    float* xep = xe + b*64*HWc + hw;
    float* xqp = xq + b*64*HWc + hw;

    #pragma unroll
    for (int c4 = 0; c4 < 16; c4++) {
        float4 oh = ohp[c4], ow = owp[c4];
        float s0 = fmaf(a, oh.x, bb*ow.x)*inv + 2.f;
        float s1 = fmaf(a, oh.y, bb*ow.y)*inv + 2.f;
        float s2 = fmaf(a, oh.z, bb*ow.z)*inv + 2.f;
        float s3 = fmaf(a, oh.w, bb*ow.w)*inv + 2.f;
        int c = c4*4;
        xep[(c+0)*HWc] = fmaf(g1, s0, xep[(c+0)*HWc]);
        xep[(c+1)*HWc] = fmaf(g1, s1, xep[(c+1)*HWc]);
        xep[(c+2)*HWc] = fmaf(g1, s2, xep[(c+2)*HWc]);
        xep[(c+3)*HWc] = fmaf(g1, s3, xep[(c+3)*HWc]);
        xqp[(c+0)*HWc] = fmaf(g2, s0, xqp[(c+0)*HWc]);
        xqp[(c+1)*HWc] = fmaf(g2, s1, xqp[(c+1)*HWc]);
        xqp[(c+2)*HWc] = fmaf(g2, s2, xqp[(c+2)*HWc]);
        xqp[(c+3)*HWc] = fmaf(g2, s3, xqp[(c+3)*HWc]);
    }
}

// ---------------- launch ----------------
extern "C" void kernel_launch(void* const* d_in, const int* in_sizes, int n_in,
                              void* d_out, int out_size)
{
    const float* x_ex   = (const float*)d_in[0];
    const float* x_qr   = (const float*)d_in[1];
    const float* cexw   = (const float*)d_in[2];
    const float* bexs   = (const float*)d_in[3];
    const float* bexb   = (const float*)d_in[4];
    const float* cqw    = (const float*)d_in[5];
    const float* bqs    = (const float*)d_in[6];
    const float* bqb    = (const float*)d_in[7];
    const float* qw     = (const float*)d_in[8];
    const float* qb     = (const float*)d_in[9];
    const float* kw     = (const float*)d_in[10];
    const float* kb     = (const float*)d_in[11];
    const float* vw     = (const float*)d_in[12];
    const float* vb     = (const float*)d_in[13];
    const float* g1     = (const float*)d_in[14];
    const float* g2     = (const float*)d_in[15];
    const float* texw   = (const float*)d_in[16];
    const float* btexs  = (const float*)d_in[17];
    const float* btexb  = (const float*)d_in[18];
    const float* tqw    = (const float*)d_in[19];
    const float* btqs   = (const float*)d_in[20];
    const float* btqb   = (const float*)d_in[21];
    float* out = (float*)d_out;

    float *p_xe,*p_xq,*p_q,*p_k,*p_vA,*p_vB,*p_OH,*p_OW,*p_mH,*p_sH,*p_mW,*p_sW;
    uint32_t *p_wkE,*p_wkQ,*p_wkTE,*p_wkTQ,*p_xh2a,*p_xh2b;
    cudaGetSymbolAddress((void**)&p_xe, g_xe);
    cudaGetSymbolAddress((void**)&p_xq, g_xq);
    cudaGetSymbolAddress((void**)&p_q,  g_q);
    cudaGetSymbolAddress((void**)&p_k,  g_k);
    cudaGetSymbolAddress((void**)&p_vA, g_vA);
    cudaGetSymbolAddress((void**)&p_vB, g_vB);
    cudaGetSymbolAddress((void**)&p_OH, g_OH);
    cudaGetSymbolAddress((void**)&p_OW, g_OW);
    cudaGetSymbolAddress((void**)&p_mH, g_mH);
    cudaGetSymbolAddress((void**)&p_sH, g_sH);
    cudaGetSymbolAddress((void**)&p_mW, g_mW);
    cudaGetSymbolAddress((void**)&p_sW, g_sW);
    cudaGetSymbolAddress((void**)&p_wkE,  g_wkE);
    cudaGetSymbolAddress((void**)&p_wkQ,  g_wkQ);
    cudaGetSymbolAddress((void**)&p_wkTE, g_wkTE);
    cudaGetSymbolAddress((void**)&p_wkTQ, g_wkTQ);
    cudaGetSymbolAddress((void**)&p_xh2a, g_xh2a);
    cudaGetSymbolAddress((void**)&p_xh2b, g_xh2b);

    // smem bytes: mainloop vs epilogue (aliased) max
    const int head_smem = (48*136 + 18*32*20) * 4;   // 72192
    const int tail_smem = (48*136 + 18*32*36) * 4;   // 109056
    cudaFuncSetAttribute((const void*)conv_mma16<256,64,1>,
                         cudaFuncAttributeMaxDynamicSharedMemorySize, head_smem);
    cudaFuncSetAttribute((const void*)conv_mma16<64,128,2>,
                         cudaFuncAttributeMaxDynamicSharedMemorySize, tail_smem);
    const size_t attn_smem = (size_t)(1024 + 1024 + 8192 + 128*128) * sizeof(float);
    cudaFuncSetAttribute((const void*)attn_kernel<true>,
                         cudaFuncAttributeMaxDynamicSharedMemorySize, (int)attn_smem);
    cudaFuncSetAttribute((const void*)attn_kernel<false>,
                         cudaFuncAttributeMaxDynamicSharedMemorySize, (int)attn_smem);

    // weight prep: 73728 half2 regs each (9*CIN*COUT/2)
    prep_frag16<<<288, 256>>>(cexw, p_wkE, 256, 64, 73728);
    prep_frag16<<<288, 256>>>(cqw,  p_wkQ, 256, 64, 73728);
    prep_frag16<<<288, 256>>>(texw, p_wkTE, 64, 128, 73728);
    prep_frag16<<<288, 256>>>(tqw,  p_wkTQ, 64, 128, 73728);

    // head input prepass: 8*128*16384 = 16777216 u32 each
    prep_half<<<65536, 256>>>(x_ex, p_xh2a, 16777216);
    prep_half<<<65536, 256>>>(x_qr, p_xh2b, 16777216);

    conv_mma16<256,64,1><<<dim3(Hc, Bc, 1), 256, head_smem>>>(p_xh2a, p_wkE, bexs, bexb, p_xe);
    conv_mma16<256,64,1><<<dim3(Hc, Bc, 1), 256, head_smem>>>(p_xh2b, p_wkQ, bqs,  bqb,  p_xq);

    for (int it = 0; it < 2; it++) {
        qkv_kernel<<<BHWc/256, 256>>>(p_xe, p_xq, qw, qb, kw, kb, vw, vb,
                                      p_q, p_k, p_vA, p_vB);
        attn_kernel<true ><<<dim3(Wc, Bc), 256, attn_smem>>>(p_q, p_k, p_vA, p_OH, p_mH, p_sH);
        attn_kernel<false><<<dim3(Hc, Bc), 256, attn_smem>>>(p_q, p_k, p_vB, p_OW, p_mW, p_sW);
        merge_kernel<<<BHWc/256, 256>>>(p_OH, p_OW, p_mH, p_sH, p_mW, p_sW,
                                        p_xe, p_xq, g1, g2);
    }

    // tail input prepass: 8*32*16384 = 4194304 u32 each
    prep_half<<<16384, 256>>>(p_xe, p_xh2a, 4194304);
    prep_half<<<16384, 256>>>(p_xq, p_xh2b, 4194304);

    conv_mma16<64,128,2><<<dim3(Hc, Bc, 2), 256, tail_smem>>>(p_xh2a, p_wkTE, btexs, btexb, out);
    conv_mma16<64,128,2><<<dim3(Hc, Bc, 2), 256, tail_smem>>>(p_xh2b, p_wkTQ, btqs, btqb,
                                                              out + (size_t)Bc*Cc*HWc);
}